// round 5
// baseline (speedup 1.0000x reference)
#include <cuda_runtime.h>

#define Nn 2048
#define Ee 4096
#define CAPV 6144
#define CAPE 20480

#define TN4 (Nn * Ee / 4)
#define VN4 (Nn * Nn / 4)
#define EN4 (Ee * Ee / 4)

// ---------------- static device scratch ----------------
static __device__ int      g_en[Ee * 2];       // two node endpoints per edge (sorted a<=b)
static __device__ int      g_ecnt[Ee];
static __device__ int      g_nnzv;
static __device__ int      g_nnze;

static __device__ float    g_vdiag[Nn];
static __device__ int      g_vi[CAPV];
static __device__ int      g_vj[CAPV];
static __device__ float    g_vval[CAPV];
static __device__ float    g_msum[CAPV];       // accumulated mult1 per adj_v nz entry
static __device__ int      g_vcnt[Nn];
static __device__ int      g_vcur[Nn];
static __device__ int      g_vptr[Nn + 1];
static __device__ int      g_vord[CAPV];

static __device__ float    g_ediag[Ee];
static __device__ int      g_ei[CAPE];
static __device__ int      g_ef[CAPE];
static __device__ float    g_eval[CAPE];
static __device__ float    g_aval[CAPE];       // mult2*adj_e per nz entry (per edge layer)
static __device__ int      g_ecnt2[Ee];
static __device__ int      g_ecur[Ee];
static __device__ int      g_eptr[Ee + 1];
static __device__ int      g_eord[CAPE];
static __device__ unsigned g_colmax[Ee];       // ordered-uint column max

static __device__ int      g_map0[Ee];         // edge -> adj_v entry (a,b)
static __device__ int      g_map1[Ee];         // edge -> adj_v entry (b,a)

static __device__ float    g_X1F1[Nn * 256];
static __device__ float    g_HWn[Nn * 128];    // reused HW1/HW3/HW5
static __device__ float    g_X3[Nn * 128];
static __device__ float    g_Z2F2[Ee * 32];
static __device__ float    g_HWe[Ee * 16];     // reused HW2/HW4
static __device__ float    g_Z4[Ee * 16];
static __device__ float    g_s[Ee];            // reused gate vector s1..s5

#define AUX_NONE   0
#define AUX_MSUM   1
#define AUX_COLMAX 2

// ---------------- helpers ----------------
__device__ __forceinline__ unsigned f2ord(float f) {
    unsigned u = __float_as_uint(f);
    return (u & 0x80000000u) ? ~u : (u | 0x80000000u);
}
__device__ __forceinline__ float ord2f(unsigned u) {
    return __uint_as_float((u & 0x80000000u) ? (u & 0x7fffffffu) : ~u);
}
__device__ __forceinline__ float blockSum128(float v) {
    #pragma unroll
    for (int o = 16; o > 0; o >>= 1) v += __shfl_xor_sync(0xffffffffu, v, o);
    __shared__ float sh[4];
    if ((threadIdx.x & 31) == 0) sh[threadIdx.x >> 5] = v;
    __syncthreads();
    float tot = sh[0] + sh[1] + sh[2] + sh[3];
    __syncthreads();
    return tot;
}

// ---------------- infra kernels ----------------
__global__ void k_clear() {
    int i = blockIdx.x * 256 + threadIdx.x;
    if (i < Ee) { g_ecnt[i] = 0; g_ecnt2[i] = 0; g_ecur[i] = 0; }
    if (i < Nn) { g_vcnt[i] = 0; g_vcur[i] = 0; }
    if (i < CAPV) g_msum[i] = 0.f;
    if (i == 0) { g_nnzv = 0; g_nnze = 0; }
}

// fused single-pass scan of T, adj_v, adj_e (disjoint output structures)
__global__ void k_scan(const float4* __restrict__ T, const float4* __restrict__ AV,
                       const float4* __restrict__ AE) {
    int idx = blockIdx.x * 256 + threadIdx.x;
    if (idx < TN4) {
        float4 v = T[idx];
        int base = idx * 4;
        int i = base / Ee;
        int e0 = base % Ee;
        float vals[4] = {v.x, v.y, v.z, v.w};
        #pragma unroll
        for (int l = 0; l < 4; l++) {
            float val = vals[l];
            if (val != 0.f) {
                int e = e0 + l;
                int k = (int)(val + 0.5f);      // 1 (endpoint) or 2 (self-loop)
                int slot = atomicAdd(&g_ecnt[e], k);
                if (slot < 2) {
                    g_en[e * 2 + slot] = i;
                    if (k == 2) g_en[e * 2 + 1] = i;
                }
            }
        }
    } else if (idx < TN4 + VN4) {
        int t = idx - TN4;
        float4 v = AV[t];
        int base = t * 4;
        int i = base / Nn;
        int j0 = base % Nn;
        float vals[4] = {v.x, v.y, v.z, v.w};
        #pragma unroll
        for (int l = 0; l < 4; l++) {
            float val = vals[l];
            if (val != 0.f) {
                int j = j0 + l;
                if (i == j) {
                    g_vdiag[i] = val;
                } else {
                    int p = atomicAdd(&g_nnzv, 1);
                    if (p < CAPV) {
                        g_vi[p] = i; g_vj[p] = j; g_vval[p] = val;
                        atomicAdd(&g_vcnt[i], 1);
                    }
                }
            }
        }
    } else {
        int t = idx - TN4 - VN4;
        float4 v = AE[t];
        int base = t * 4;
        int e = base / Ee;
        int f0 = base % Ee;
        float vals[4] = {v.x, v.y, v.z, v.w};
        #pragma unroll
        for (int l = 0; l < 4; l++) {
            float val = vals[l];
            if (val != 0.f) {
                int f = f0 + l;
                if (e == f) {
                    g_ediag[e] = val;
                } else {
                    int p = atomicAdd(&g_nnze, 1);
                    if (p < CAPE) {
                        g_ei[p] = e; g_ef[p] = f; g_eval[p] = val;
                        atomicAdd(&g_ecnt2[e], 1);
                    }
                }
            }
        }
    }
}

__device__ void prefix_scan(const int* cnt, int* ptr, int n) {
    __shared__ int sh[1024];
    int t = threadIdx.x;
    int per = (n + 1023) / 1024;
    int base = t * per;
    int s = 0;
    for (int k = 0; k < per; k++) { int id = base + k; s += (id < n) ? cnt[id] : 0; }
    sh[t] = s;
    __syncthreads();
    for (int off = 1; off < 1024; off <<= 1) {
        int v = (t >= off) ? sh[t - off] : 0;
        __syncthreads();
        sh[t] += v;
        __syncthreads();
    }
    int run = (t > 0) ? sh[t - 1] : 0;
    for (int k = 0; k < per; k++) {
        int id = base + k;
        if (id < n) { ptr[id] = run; run += cnt[id]; }
    }
    if (t == 1023) ptr[n] = sh[1023];
}
__global__ void k_pref() {
    if (blockIdx.x == 0) prefix_scan(g_vcnt, g_vptr, Nn);
    else                 prefix_scan(g_ecnt2, g_eptr, Ee);
}

__global__ void k_fill() {
    int idx = blockIdx.x * blockDim.x + threadIdx.x;
    int nv = g_nnzv; if (nv > CAPV) nv = CAPV;
    if (idx < nv) {
        int r = g_vi[idx];
        int pos = g_vptr[r] + atomicAdd(&g_vcur[r], 1);
        g_vord[pos] = idx;
    }
    int ne = g_nnze; if (ne > CAPE) ne = CAPE;
    if (idx < ne) {
        int r = g_ei[idx];
        int pos = g_eptr[r] + atomicAdd(&g_ecur[r], 1);
        g_eord[pos] = idx;
    }
}

// deterministic per-row order (keys unique per row)
__global__ void k_sort() {
    int r = blockIdx.x * blockDim.x + threadIdx.x;
    if (r < Nn) {
        int lo = g_vptr[r], hi = g_vptr[r + 1];
        for (int p = lo + 1; p < hi; p++) {
            int id = g_vord[p]; int key = g_vj[id]; int q = p - 1;
            while (q >= lo && g_vj[g_vord[q]] > key) { g_vord[q + 1] = g_vord[q]; q--; }
            g_vord[q + 1] = id;
        }
    } else if (r < Nn + Ee) {
        int e = r - Nn;
        int lo = g_eptr[e], hi = g_eptr[e + 1];
        for (int p = lo + 1; p < hi; p++) {
            int id = g_eord[p]; int key = g_ef[id]; int q = p - 1;
            while (q >= lo && g_ef[g_eord[q]] > key) { g_eord[q + 1] = g_eord[q]; q--; }
            g_eord[q + 1] = id;
        }
    }
}

__device__ __forceinline__ int find_entry(int row, int col) {
    int lo = g_vptr[row], hi = g_vptr[row + 1];
    for (int p = lo; p < hi; p++) {
        int id = g_vord[p];
        if (g_vj[id] == col) return id;
    }
    return -1;
}
__global__ void k_map() {
    int e = blockIdx.x * blockDim.x + threadIdx.x;
    if (e >= Ee) return;
    int a = g_en[2 * e], b = g_en[2 * e + 1];
    if (a > b) { int t = a; a = b; b = t; g_en[2 * e] = a; g_en[2 * e + 1] = b; }
    if (a == b) { g_map0[e] = -1; g_map1[e] = -1; return; }
    g_map0[e] = find_entry(a, b);
    g_map1[e] = find_entry(b, a);
}

// ---------------- fused layer-front kernel ----------------
// Independent roles dispatched by blockIdx range (all 128-thread blocks):
//   [0,n1)            gemm128 job1   (row = rel)
//   [n1,n1+n2)        gemm128 job2
//   [.. +n3)          gemm16 job     (8 rows per block)
//   [.. +n4)          dot job        (4 rows per block, warp per row)
//   tail              aux (msum clear | colmax seed)
__device__ __forceinline__ void do_gemm128(int r, const float* __restrict__ A, int lda,
                                           int K, const float* __restrict__ B,
                                           float* __restrict__ out, int ldc, int ocol,
                                           int fuse_ln, const float* __restrict__ g,
                                           const float* __restrict__ be, float* As) {
    int c = threadIdx.x;
    for (int k = c; k < K; k += 128) As[k] = A[r * lda + k];
    __syncthreads();
    float acc = 0.f;
    #pragma unroll 8
    for (int k = 0; k < K; k++) acc += As[k] * B[k * 128 + c];
    if (fuse_ln) {
        float mean = blockSum128(acc) * (1.f / 128.f);
        float d = acc - mean;
        float var = blockSum128(d * d) * (1.f / 128.f);
        acc = fmaxf(d * rsqrtf(var + 1e-5f) * g[c] + be[c], 0.f);
    }
    out[r * ldc + ocol + c] = acc;
}

__device__ __forceinline__ void do_gemm16(int blk, const float* __restrict__ A, int lda,
                                          int K, const float* __restrict__ B,
                                          float* __restrict__ out, int ldc, int ocol,
                                          int reluA, int fuse_ln,
                                          const float* __restrict__ g,
                                          const float* __restrict__ be, float* Asf) {
    float (*As)[32] = (float (*)[32])Asf;
    int t = threadIdx.x;
    int rg = t >> 4, c = t & 15;
    int r = blk * 8 + rg;
    for (int k = c; k < K; k += 16) {
        float v = A[r * lda + k];
        if (reluA) v = fmaxf(v, 0.f);
        As[rg][k] = v;
    }
    __syncthreads();
    float acc = 0.f;
    #pragma unroll 8
    for (int k = 0; k < K; k++) acc += As[rg][k] * B[k * 16 + c];
    if (fuse_ln) {
        float s = acc;
        #pragma unroll
        for (int o = 8; o > 0; o >>= 1) s += __shfl_xor_sync(0xffffffffu, s, o, 16);
        float mean = s * (1.f / 16.f);
        float d = acc - mean;
        float s2 = d * d;
        #pragma unroll
        for (int o = 8; o > 0; o >>= 1) s2 += __shfl_xor_sync(0xffffffffu, s2, o, 16);
        float var = s2 * (1.f / 16.f);
        acc = fmaxf(d * rsqrtf(var + 1e-5f) * g[c] + be[c], 0.f);
    }
    out[r * ldc + ocol + c] = acc;
}

__global__ void k_fused(
    int n1, const float* __restrict__ A1, int lda1, int K1, const float* __restrict__ B1,
    float* __restrict__ O1, int ldc1, int oc1, int ln1,
    const float* __restrict__ g1, const float* __restrict__ be1,
    int n2, const float* __restrict__ A2, int lda2, int K2, const float* __restrict__ B2,
    float* __restrict__ O2, int ldc2, int oc2, int ln2,
    const float* __restrict__ g2, const float* __restrict__ be2,
    int n3, const float* __restrict__ A3, int lda3, int K3, const float* __restrict__ B3,
    float* __restrict__ O3, int ldc3, int oc3, int relu3, int ln3,
    const float* __restrict__ g3, const float* __restrict__ be3,
    int n4, const float* __restrict__ A4, int lda4, int K4, const float* __restrict__ p4,
    int R4, int aux)
{
    __shared__ float sh[256];
    int b = blockIdx.x;
    if (b < n1) {
        do_gemm128(b, A1, lda1, K1, B1, O1, ldc1, oc1, ln1, g1, be1, sh);
        return;
    }
    b -= n1;
    if (b < n2) {
        do_gemm128(b, A2, lda2, K2, B2, O2, ldc2, oc2, ln2, g2, be2, sh);
        return;
    }
    b -= n2;
    if (b < n3) {
        do_gemm16(b, A3, lda3, K3, B3, O3, ldc3, oc3, relu3, ln3, g3, be3, sh);
        return;
    }
    b -= n3;
    if (b < n4) {
        int w = b * 4 + (threadIdx.x >> 5);
        int lane = threadIdx.x & 31;
        if (w < R4) {
            float acc = 0.f;
            for (int k = lane; k < K4; k += 32) acc += A4[w * lda4 + k] * p4[k];
            #pragma unroll
            for (int o = 16; o > 0; o >>= 1) acc += __shfl_xor_sync(0xffffffffu, acc, o);
            if (lane == 0) g_s[w] = acc;
        }
        return;
    }
    b -= n4;
    int i = b * 128 + threadIdx.x;
    if (aux == AUX_MSUM) {
        if (i < CAPV) g_msum[i] = 0.f;
    } else if (aux == AUX_COLMAX) {
        if (i < Ee) g_colmax[i] = f2ord(g_ediag[i]);
    }
}

// ---------------- sparse apply kernels ----------------
__global__ void k_scatter_node() {
    int e = blockIdx.x * blockDim.x + threadIdx.x;
    if (e >= Ee) return;
    int a = g_en[2 * e], b = g_en[2 * e + 1];
    if (a == b) return;
    float sv = g_s[e];
    int m0 = g_map0[e]; if (m0 >= 0) atomicAdd(&g_msum[m0], sv);
    int m1 = g_map1[e]; if (m1 >= 0) atomicAdd(&g_msum[m1], sv);
}

__global__ void k_gather_node(const float* __restrict__ bias, float* __restrict__ out,
                              int ldc, int relu) {
    int i = blockIdx.x, c = threadIdx.x;
    float acc = bias[c] + g_vdiag[i] * g_HWn[i * 128 + c];
    int lo = g_vptr[i], hi = g_vptr[i + 1];
    for (int p = lo; p < hi; p++) {
        int id = g_vord[p];
        acc += g_msum[id] * g_vval[id] * g_HWn[g_vj[id] * 128 + c];
    }
    if (relu) acc = fmaxf(acc, 0.f);
    out[i * ldc + c] = acc;
}

__global__ void k_edge_entries() {
    int idx = blockIdx.x * blockDim.x + threadIdx.x;
    int nn = g_nnze; if (nn > CAPE) nn = CAPE;
    if (idx >= nn) return;
    int e = g_ei[idx], f = g_ef[idx];
    int a0 = g_en[2 * e], a1 = g_en[2 * e + 1];
    int b0 = g_en[2 * f], b1 = g_en[2 * f + 1];
    float m = g_s[a0] * ((float)(a0 == b0) + (float)(a0 == b1))
            + g_s[a1] * ((float)(a1 == b0) + (float)(a1 == b1));
    float av = m * g_eval[idx];
    g_aval[idx] = av;
    atomicMax(&g_colmax[f], f2ord(av));
}

__global__ void k_gather_edge(const float* __restrict__ bias, float* __restrict__ out,
                              int ldc, int relu) {
    int t = threadIdx.x;
    int e = blockIdx.x * 8 + (t >> 4);
    int c = t & 15;
    float acc = bias[c] + g_ediag[e] * (1.f / ord2f(g_colmax[e])) * g_HWe[e * 16 + c];
    int lo = g_eptr[e], hi = g_eptr[e + 1];
    for (int p = lo; p < hi; p++) {
        int id = g_eord[p];
        int f = g_ef[id];
        acc += g_aval[id] * (1.f / ord2f(g_colmax[f])) * g_HWe[f * 16 + c];
    }
    if (relu) acc = fmaxf(acc, 0.f);
    out[e * ldc + c] = acc;
}

// ---------------- host launcher ----------------
extern "C" void kernel_launch(void* const* d_in, const int* in_sizes, int n_in,
                              void* d_out, int out_size) {
    (void)in_sizes; (void)n_in; (void)out_size;
    const float* X     = (const float*)d_in[0];
    const float* Z     = (const float*)d_in[1];
    const float* adj_e = (const float*)d_in[2];
    const float* adj_v = (const float*)d_in[3];
    const float* T     = (const float*)d_in[4];
    const float* W1  = (const float*)d_in[5];
    const float* p1  = (const float*)d_in[6];
    const float* b1  = (const float*)d_in[7];
    const float* Wf1 = (const float*)d_in[8];
    const float* g1  = (const float*)d_in[9];
    const float* be1 = (const float*)d_in[10];
    const float* W2  = (const float*)d_in[11];
    const float* p2  = (const float*)d_in[12];
    const float* b2  = (const float*)d_in[13];
    const float* Wf2 = (const float*)d_in[14];
    const float* g2  = (const float*)d_in[15];
    const float* be2 = (const float*)d_in[16];
    const float* W3  = (const float*)d_in[17];
    const float* p3  = (const float*)d_in[18];
    const float* b3  = (const float*)d_in[19];
    const float* W4  = (const float*)d_in[20];
    const float* p4  = (const float*)d_in[21];
    const float* b4  = (const float*)d_in[22];
    const float* W5  = (const float*)d_in[23];
    const float* p5  = (const float*)d_in[24];
    const float* b5  = (const float*)d_in[25];
    float* out = (float*)d_out;

    float *X1F1, *HWn, *HWe, *X3, *Z2F2, *Z4;
    cudaGetSymbolAddress((void**)&X1F1, g_X1F1);
    cudaGetSymbolAddress((void**)&HWn,  g_HWn);
    cudaGetSymbolAddress((void**)&HWe,  g_HWe);
    cudaGetSymbolAddress((void**)&X3,   g_X3);
    cudaGetSymbolAddress((void**)&Z2F2, g_Z2F2);
    cudaGetSymbolAddress((void**)&Z4,   g_Z4);

    const int AUXV = CAPV / 128;   // 48 blocks clear msum
    const int AUXE = Ee / 128;     // 32 blocks seed colmax
    const int DOTE = Ee / 4;       // 1024 dot blocks over edges
    const int DOTN = Nn / 4;       // 512 dot blocks over nodes

    // ---- sparsity extraction ----
    k_clear<<<CAPV / 256, 256>>>();
    k_scan<<<(TN4 + VN4 + EN4) / 256, 256>>>((const float4*)T, (const float4*)adj_v,
                                             (const float4*)adj_e);
    k_pref<<<2, 1024>>>();
    k_fill<<<CAPE / 256, 256>>>();
    k_sort<<<(Nn + Ee) / 128, 128>>>();
    k_map<<<Ee / 256, 256>>>();

    // ---- precompute: HW1 + F1(LN) + F2(LN) + s1 in one launch ----
    k_fused<<<Nn + Nn + Ee / 8 + DOTE, 128>>>(
        Nn, X, 64, 64, W1, HWn, 128, 0, 0, 0, 0,
        Nn, X, 64, 64, Wf1, X1F1, 256, 128, 1, g1, be1,
        Ee / 8, Z, 16, 16, Wf2, Z2F2, 32, 16, 0, 1, g2, be2,
        DOTE, Z, 16, 16, p1, Ee, AUX_NONE);

    // ---- gc1 (node): X1 -> X1F1[:, :128] ----
    k_scatter_node<<<Ee / 256, 256>>>();   // msum zeroed by k_clear
    k_gather_node<<<Nn, 128>>>(b1, X1F1, 256, 1);

    // ---- gc2 (edge): s2 + HW2 + colmax seed, then entries, gather ----
    k_fused<<<Ee / 8 + DOTN + AUXE, 128>>>(
        0, 0, 0, 0, 0, 0, 0, 0, 0, 0, 0,
        0, 0, 0, 0, 0, 0, 0, 0, 0, 0, 0,
        Ee / 8, Z, 16, 16, W2, HWe, 16, 0, 1, 0, 0, 0,
        DOTN, X1F1, 256, 256, p2, Nn, AUX_COLMAX);
    k_edge_entries<<<CAPE / 256, 256>>>();
    k_gather_edge<<<Ee / 8, 128>>>(b2, Z2F2, 32, 1);

    // ---- gc3 (node): s3 + HW3 + msum clear, then scatter, gather ----
    k_fused<<<Nn + DOTE + AUXV, 128>>>(
        Nn, X1F1, 256, 256, W3, HWn, 128, 0, 0, 0, 0,
        0, 0, 0, 0, 0, 0, 0, 0, 0, 0, 0,
        0, 0, 0, 0, 0, 0, 0, 0, 0, 0, 0, 0,
        DOTE, Z2F2, 32, 32, p3, Ee, AUX_MSUM);
    k_scatter_node<<<Ee / 256, 256>>>();
    k_gather_node<<<Nn, 128>>>(b3, X3, 128, 1);

    // ---- gc4 (edge): s4 + HW4 + colmax seed ----
    k_fused<<<Ee / 8 + DOTN + AUXE, 128>>>(
        0, 0, 0, 0, 0, 0, 0, 0, 0, 0, 0,
        0, 0, 0, 0, 0, 0, 0, 0, 0, 0, 0,
        Ee / 8, Z2F2, 32, 32, W4, HWe, 16, 0, 0, 0, 0, 0,
        DOTN, X3, 128, 128, p4, Nn, AUX_COLMAX);
    k_edge_entries<<<CAPE / 256, 256>>>();
    k_gather_edge<<<Ee / 8, 128>>>(b4, Z4, 16, 1);

    // ---- gc5 (node): s5 + HW5 + msum clear; out has no relu ----
    k_fused<<<Nn + DOTE + AUXV, 128>>>(
        Nn, X3, 128, 128, W5, HWn, 128, 0, 0, 0, 0,
        0, 0, 0, 0, 0, 0, 0, 0, 0, 0, 0,
        0, 0, 0, 0, 0, 0, 0, 0, 0, 0, 0, 0,
        DOTE, Z4, 16, 16, p5, Ee, AUX_MSUM);
    k_scatter_node<<<Ee / 256, 256>>>();
    k_gather_node<<<Nn, 128>>>(b5, out, 128, 0);
}